// round 14
// baseline (speedup 1.0000x reference)
#include <cuda_runtime.h>
#include <cstdint>

#define C 32
#define BMAX 16
#define EPS 1e-5f

// TMA-staged reduce pipeline geometry (static smem: 4 x 8KB = 32KB + mbars)
#define STAGES 4
#define STAGE_ROWS 64
#define STAGE_BYTES (STAGE_ROWS * C * 4)   // 8192

// Scratch (device globals: zero-initialized at module load; finalize_kernel
// resets them after consuming, so every graph replay starts clean).
__device__ float g_sum[BMAX * C];
__device__ float g_sq[BMAX * C];
__device__ float g_cnt[BMAX];
__device__ float g_scale[BMAX * C];
__device__ float g_shift[BMAX * C];

// ---------------------------------------------------------------------------
// PTX helpers (1-D bulk TMA + mbarrier)
// ---------------------------------------------------------------------------
__device__ __forceinline__ uint32_t smem_u32(const void* p) {
    uint32_t a;
    asm("{ .reg .u64 t; cvta.to.shared.u64 t, %1; cvt.u32.u64 %0, t; }"
        : "=r"(a) : "l"(p));
    return a;
}
__device__ __forceinline__ void mbar_init(uint32_t m, uint32_t cnt) {
    asm volatile("mbarrier.init.shared.b64 [%0], %1;"
                 :: "r"(m), "r"(cnt) : "memory");
}
__device__ __forceinline__ void mbar_expect_tx(uint32_t m, uint32_t bytes) {
    asm volatile("mbarrier.arrive.expect_tx.shared.b64 _, [%0], %1;"
                 :: "r"(m), "r"(bytes) : "memory");
}
__device__ __forceinline__ void bulk_g2s(uint32_t dst, const void* src,
                                         uint32_t bytes, uint32_t m) {
    asm volatile(
        "cp.async.bulk.shared::cluster.global.mbarrier::complete_tx::bytes "
        "[%0], [%1], %2, [%3];"
        :: "r"(dst), "l"(src), "r"(bytes), "r"(m) : "memory");
}
__device__ __forceinline__ void mbar_wait(uint32_t m, uint32_t parity) {
    uint32_t done;
    asm volatile(
        "{\n\t.reg .pred p;\n\t"
        "mbarrier.try_wait.parity.acquire.cta.shared::cta.b64 p, [%1], %2;\n\t"
        "selp.b32 %0, 1, 0, p;\n\t}"
        : "=r"(done) : "r"(m), "r"(parity) : "memory");
    if (!done) {
        asm volatile(
            "{\n\t.reg .pred P1;\n\t"
            "WL_%=:\n\t"
            "mbarrier.try_wait.parity.acquire.cta.shared::cta.b64 P1, [%0], %1, 0x989680;\n\t"
            "@P1 bra.uni WD_%=;\n\t"
            "bra.uni WL_%=;\n\t"
            "WD_%=:\n\t}"
            :: "r"(m), "r"(parity) : "memory");
    }
}
__device__ __forceinline__ void fence_proxy_async_cta() {
    asm volatile("fence.proxy.async.shared::cta;" ::: "memory");
}

// ---------------------------------------------------------------------------
// Shared accumulate / flush pieces
// ---------------------------------------------------------------------------
__device__ __forceinline__ void acc4(const float4& v, float4& s, float4& q) {
    s.x += v.x; s.y += v.y; s.z += v.z; s.w += v.w;
    q.x = fmaf(v.x, v.x, q.x); q.y = fmaf(v.y, v.y, q.y);
    q.z = fmaf(v.z, v.z, q.z); q.w = fmaf(v.w, v.w, q.w);
}

// Cross-lane combine (lanes sharing channels: rg = lane>>3) + atomic flush.
__device__ __forceinline__ void flush_stats(float4 s, float4 q, int b,
                                            int lane) {
    int sub = lane & 7;
    int rg  = lane >> 3;
    #pragma unroll
    for (int off = 16; off >= 8; off >>= 1) {
        s.x += __shfl_xor_sync(0xffffffffu, s.x, off);
        s.y += __shfl_xor_sync(0xffffffffu, s.y, off);
        s.z += __shfl_xor_sync(0xffffffffu, s.z, off);
        s.w += __shfl_xor_sync(0xffffffffu, s.w, off);
        q.x += __shfl_xor_sync(0xffffffffu, q.x, off);
        q.y += __shfl_xor_sync(0xffffffffu, q.y, off);
        q.z += __shfl_xor_sync(0xffffffffu, q.z, off);
        q.w += __shfl_xor_sync(0xffffffffu, q.w, off);
    }
    if (rg == 0) {
        int b4 = b * C + sub * 4;
        atomicAdd(&g_sum[b4 + 0], s.x);
        atomicAdd(&g_sum[b4 + 1], s.y);
        atomicAdd(&g_sum[b4 + 2], s.z);
        atomicAdd(&g_sum[b4 + 3], s.w);
        atomicAdd(&g_sq[b4 + 0], q.x);
        atomicAdd(&g_sq[b4 + 1], q.y);
        atomicAdd(&g_sq[b4 + 2], q.z);
        atomicAdd(&g_sq[b4 + 3], q.w);
    }
}

// Direct-LDG warp accumulation of one single-segment run [rs, re).
// Used ONLY by boundary CTAs (<=15); the streaming interior goes via TMA.
__device__ __forceinline__ void accum_run(const float* __restrict__ data,
                                          int rs, int re, int b, int lane) {
    int rows = re - rs;
    if (rows <= 0) return;
    int sub = lane & 7;
    int rg  = lane >> 3;

    const float4* base = reinterpret_cast<const float4*>(
        data + (size_t)rs * C) + (size_t)rg * 8 + sub;

    float4 s = make_float4(0.f, 0.f, 0.f, 0.f);
    float4 q = make_float4(0.f, 0.f, 0.f, 0.f);

    int nch = rows >> 3;               // full 8-row chunks
    int r = nch << 3;
    if (nch > 0) {
        float4 a = base[0];
        float4 c = base[32];
        for (int k = 1; k < nch; ++k) {
            const float4* p = base + (size_t)k * 64;
            float4 a2 = p[0];
            float4 c2 = p[32];
            acc4(a, s, q); acc4(c, s, q);
            a = a2; c = c2;
        }
        acc4(a, s, q); acc4(c, s, q);
    }
    if (r + 4 <= rows) {
        float4 a = base[(size_t)r * 8];
        acc4(a, s, q);
        r += 4;
    }
    if (r < rows && r + rg < rows) {
        float4 a = base[(size_t)r * 8];
        acc4(a, s, q);
    }

    flush_stats(s, q, b, lane);
    if (lane == 0) atomicAdd(&g_cnt[b], (float)rows);
}

// ---------------------------------------------------------------------------
// Kernel 1: per-segment sum / sumsq / count.
// Interior CTAs (single segment, ~all of them): HBM -> SMEM via 4-stage
// cp.async.bulk pipeline (TMA bypasses the per-SM outstanding-LDG cap that
// capped the direct path at ~5 TB/s across R9-R13), consumed with
// conflict-free LDS.128. Boundary CTAs: direct-LDG runs per warp.
// ---------------------------------------------------------------------------
__global__ void reduce_kernel(const float* __restrict__ data,
                              const int* __restrict__ bid,
                              int N, int rows_per_cta) {
    __shared__ __align__(128) float4 st_buf[STAGES][STAGE_ROWS * 8];
    __shared__ __align__(8) unsigned long long st_mbar[STAGES];

    int tid = threadIdx.x;
    int wid = tid >> 5;
    int lane = tid & 31;

    int r0 = blockIdx.x * rows_per_cta;
    if (r0 >= N) return;
    int r1 = r0 + rows_per_cta;
    if (r1 > N) r1 = N;

    int b_first = bid[r0];
    int b_last = bid[r1 - 1];

    if (b_first != b_last) {
        // ---- Boundary CTA (<=15): split chunk among 8 warps, direct LDG.
        int rows = r1 - r0;
        int rpw = (rows + 7) >> 3;
        int w0 = r0 + wid * rpw;
        if (w0 < r1) {
            int w1 = w0 + rpw;
            if (w1 > r1) w1 = r1;
            int bf = bid[w0], bl = bid[w1 - 1];
            if (bf == bl) {
                accum_run(data, w0, w1, bf, lane);
            } else {
                int r = w0;
                int b = bf;
                while (r < w1) {
                    int lo = r + 1, hi = w1;
                    while (lo < hi) {             // binary search run end
                        int mid = (lo + hi) >> 1; // broadcast load
                        if (bid[mid] == b) lo = mid + 1;
                        else hi = mid;
                    }
                    accum_run(data, r, lo, b, lane);
                    r = lo;
                    if (r < w1) b = bid[r];
                }
            }
        }
        return;
    }

    // ---- Interior CTA: TMA-staged streaming reduce ----
    int rows = r1 - r0;
    int nstages = (rows + STAGE_ROWS - 1) / STAGE_ROWS;

    uint32_t mb0 = smem_u32(&st_mbar[0]);
    if (tid == 0) {
        #pragma unroll
        for (int s = 0; s < STAGES; ++s) mbar_init(mb0 + 8u * s, 1);
    }
    __syncthreads();

    const char* gsrc = reinterpret_cast<const char*>(data + (size_t)r0 * C);

    if (tid == 0) {
        int pre = nstages < STAGES ? nstages : STAGES;
        for (int s = 0; s < pre; ++s) {
            int sr = rows - s * STAGE_ROWS;
            if (sr > STAGE_ROWS) sr = STAGE_ROWS;
            uint32_t bytes = (uint32_t)sr * (C * 4);
            uint32_t mb = mb0 + 8u * s;
            mbar_expect_tx(mb, bytes);
            bulk_g2s(smem_u32(&st_buf[s][0]),
                     gsrc + (size_t)s * STAGE_BYTES, bytes, mb);
        }
    }

    float4 s = make_float4(0.f, 0.f, 0.f, 0.f);
    float4 q = make_float4(0.f, 0.f, 0.f, 0.f);
    int sub = lane & 7;
    int rg  = lane >> 3;
    int row0 = wid * 8 + rg;           // this lane's first row in each stage

    for (int it = 0; it < nstages; ++it) {
        int st = it & (STAGES - 1);
        uint32_t parity = (uint32_t)((it >> 2) & 1);   // STAGES == 4
        uint32_t mb = mb0 + 8u * st;
        mbar_wait(mb, parity);

        int sr = rows - it * STAGE_ROWS;
        if (sr > STAGE_ROWS) sr = STAGE_ROWS;
        const float4* sb = &st_buf[st][0];
        if (row0 < sr) {
            float4 a = sb[row0 * 8 + sub];
            acc4(a, s, q);
        }
        if (row0 + 4 < sr) {
            float4 a = sb[(row0 + 4) * 8 + sub];
            acc4(a, s, q);
        }
        __syncthreads();               // all reads of this stage done

        if (tid == 0) {
            int nx = it + STAGES;
            if (nx < nstages) {
                int sr2 = rows - nx * STAGE_ROWS;
                if (sr2 > STAGE_ROWS) sr2 = STAGE_ROWS;
                uint32_t bytes = (uint32_t)sr2 * (C * 4);
                fence_proxy_async_cta();
                mbar_expect_tx(mb, bytes);
                bulk_g2s(smem_u32(&st_buf[st][0]),
                         gsrc + (size_t)nx * STAGE_BYTES, bytes, mb);
            }
        }
    }

    flush_stats(s, q, b_first, lane);
    if (tid == 0) atomicAdd(&g_cnt[b_first], (float)rows);
}

// ---------------------------------------------------------------------------
// Kernel 2: fold stats into per-(b,c) scale/shift, THEN reset the
// accumulators to zero so the next graph replay starts clean.
// ---------------------------------------------------------------------------
__global__ void finalize_kernel(const float* __restrict__ w,
                                const float* __restrict__ bias) {
    int i = threadIdx.x;           // 0..BMAX*C-1
    if (i >= BMAX * C) return;
    int b = i / C, c = i % C;
    float cnt = g_cnt[b];
    float norm = 1.0f / (cnt + EPS);
    float sum = g_sum[i];
    float mean = sum * norm;
    float var = (g_sq[i] - 2.0f * mean * sum + mean * mean * cnt) * norm;
    float inv_std = rsqrtf(var + EPS);
    float wc = w ? w[c] : 1.0f;
    float bc = bias ? bias[c] : 0.0f;
    float sc = inv_std * wc;
    g_scale[i] = sc;
    g_shift[i] = bc - mean * sc;
    // Consume-and-reset for the next replay.
    g_sum[i] = 0.0f;
    g_sq[i] = 0.0f;
    if (c == 0) g_cnt[b] = 0.0f;
}

// ---------------------------------------------------------------------------
// Normalize one single-segment run [rs, re): scale/shift in registers,
// inner loop pure LDG.128 -> FMA -> STG.128 with one-chunk lookahead.
// [R10: 6.4 TB/s effective — at ceiling, unchanged]
// ---------------------------------------------------------------------------
__device__ __forceinline__ void norm_run(const float* __restrict__ data,
                                         float* __restrict__ out,
                                         const float4* s_scale,
                                         const float4* s_shift,
                                         int rs, int re, int b, int lane) {
    int rows = re - rs;
    if (rows <= 0) return;
    int sub = lane & 7;
    int rg  = lane >> 3;

    float4 sc = s_scale[b * 8 + sub];   // once per run
    float4 sh = s_shift[b * 8 + sub];

    const float4* pi = reinterpret_cast<const float4*>(
        data + (size_t)rs * C) + (size_t)rg * 8 + sub;
    float4* po = reinterpret_cast<float4*>(
        out + (size_t)rs * C) + (size_t)rg * 8 + sub;

    int nch = rows >> 3;               // full 8-row chunks
    int r = nch << 3;
    if (nch > 0) {
        float4 a = __ldcs(pi);
        float4 c = __ldcs(pi + 32);
        for (int k = 1; k < nch; ++k) {
            const float4* p = pi + (size_t)k * 64;
            float4 a2 = __ldcs(p);         // prefetch chunk k
            float4 c2 = __ldcs(p + 32);
            float4 o0, o1;
            o0.x = fmaf(a.x, sc.x, sh.x); o0.y = fmaf(a.y, sc.y, sh.y);
            o0.z = fmaf(a.z, sc.z, sh.z); o0.w = fmaf(a.w, sc.w, sh.w);
            o1.x = fmaf(c.x, sc.x, sh.x); o1.y = fmaf(c.y, sc.y, sh.y);
            o1.z = fmaf(c.z, sc.z, sh.z); o1.w = fmaf(c.w, sc.w, sh.w);
            float4* po_k = po + (size_t)(k - 1) * 64;
            __stcs(po_k, o0);
            __stcs(po_k + 32, o1);
            a = a2; c = c2;
        }
        float4 o0, o1;
        o0.x = fmaf(a.x, sc.x, sh.x); o0.y = fmaf(a.y, sc.y, sh.y);
        o0.z = fmaf(a.z, sc.z, sh.z); o0.w = fmaf(a.w, sc.w, sh.w);
        o1.x = fmaf(c.x, sc.x, sh.x); o1.y = fmaf(c.y, sc.y, sh.y);
        o1.z = fmaf(c.z, sc.z, sh.z); o1.w = fmaf(c.w, sc.w, sh.w);
        float4* po_k = po + (size_t)(nch - 1) * 64;
        __stcs(po_k, o0);
        __stcs(po_k + 32, o1);
    }
    if (r + 4 <= rows) {
        float4 a = __ldcs(pi + (size_t)r * 8);
        float4 o;
        o.x = fmaf(a.x, sc.x, sh.x); o.y = fmaf(a.y, sc.y, sh.y);
        o.z = fmaf(a.z, sc.z, sh.z); o.w = fmaf(a.w, sc.w, sh.w);
        __stcs(po + (size_t)r * 8, o);
        r += 4;
    }
    if (r < rows && r + rg < rows) {   // 1-3 remaining rows, predicated
        float4 a = __ldcs(pi + (size_t)r * 8);
        float4 o;
        o.x = fmaf(a.x, sc.x, sh.x); o.y = fmaf(a.y, sc.y, sh.y);
        o.z = fmaf(a.z, sc.z, sh.z); o.w = fmaf(a.w, sc.w, sh.w);
        __stcs(po + (size_t)r * 8, o);
    }
}

// ---------------------------------------------------------------------------
// Kernel 3: normalize, warp-chunked.
// ---------------------------------------------------------------------------
__global__ void normalize_kernel(const float* __restrict__ data,
                                 const int* __restrict__ bid,
                                 float* __restrict__ out,
                                 int N, int rows_per_warp) {
    __shared__ float4 s_scale[BMAX * C / 4];
    __shared__ float4 s_shift[BMAX * C / 4];
    for (int i = threadIdx.x; i < BMAX * C / 4; i += blockDim.x) {
        s_scale[i] = reinterpret_cast<const float4*>(g_scale)[i];
        s_shift[i] = reinterpret_cast<const float4*>(g_shift)[i];
    }
    __syncthreads();

    int warp = (int)((blockIdx.x * blockDim.x + threadIdx.x) >> 5);
    int lane = threadIdx.x & 31;

    int r0 = warp * rows_per_warp;
    if (r0 >= N) return;
    int r1 = r0 + rows_per_warp;
    if (r1 > N) r1 = N;

    int b_first = bid[r0];
    int b_last = bid[r1 - 1];

    if (b_first == b_last) {
        norm_run(data, out, s_scale, s_shift, r0, r1, b_first, lane);
    } else {
        int r = r0;
        int b = b_first;
        while (r < r1) {
            int lo = r + 1, hi = r1;
            while (lo < hi) {
                int mid = (lo + hi) >> 1;     // broadcast load
                if (bid[mid] == b) lo = mid + 1;
                else hi = mid;
            }
            norm_run(data, out, s_scale, s_shift, r, lo, b, lane);
            r = lo;
            if (r < r1) b = bid[r];
        }
    }
}

// ---------------------------------------------------------------------------
extern "C" void kernel_launch(void* const* d_in, const int* in_sizes, int n_in,
                              void* d_out, int out_size) {
    const float* data = (const float*)d_in[0];
    const int* bid = (const int*)d_in[1];
    int N = in_sizes[0] / C;

    // Locate weights/bias among the remaining inputs (size-32 fp32 arrays).
    const float* w = nullptr;
    const float* bias = nullptr;
    for (int i = 2; i < n_in; ++i) {
        if (in_sizes[i] == C) {
            if (!w) w = (const float*)d_in[i];
            else if (!bias) bias = (const float*)d_in[i];
        }
    }

    const int threads = 256;

    // Reduce: single wave, 4 CTAs/SM (32KB static smem each), TMA-staged.
    {
        const int blocks = 148 * 4;
        int rpc = (N + blocks - 1) / blocks;
        reduce_kernel<<<blocks, threads>>>(data, bid, N, rpc);
    }

    finalize_kernel<<<1, BMAX * C>>>(w, bias);

    // Normalize: single wave at 8 blocks/SM (R10-validated config).
    {
        const int blocks = 148 * 8;
        int warps = blocks * (threads / 32);
        int rpw = (N + warps - 1) / warps;
        normalize_kernel<<<blocks, threads>>>(data, bid, (float*)d_out,
                                              N, rpw);
    }
}